// round 8
// baseline (speedup 1.0000x reference)
#include <cuda_runtime.h>
#include <cuda_fp16.h>
#include <cstdint>

// ============================================================================
// GLinear on plain sm_103 target (tcgen05 unavailable in this toolchain):
//   pack:   x[P,C,16] f32 -> 16 fp16 planes g_xh[d][P*C]  (coalesced transpose)
//   wsplit: W f32 -> fp16
//   gemm:   CTA = 32p x 64o x 8d  -> epilogue moves 32B-aligned 32B chunks
//           (exactly one DRAM sector; dg=0/1 CTAs touch disjoint sectors).
//           cp.async double-buffer + ldmatrix + mma.sync m16n8k16, 2 CTAs/SM.
// ============================================================================

static constexpr int PC = 8192 * 256;            // 2097152
__device__ __half g_xh[16][PC];                  // 64 MB packed x (fp16)
__device__ __half g_Wh[3][65536];

// ---------------------------------------------------------------------------
__device__ __forceinline__ uint32_t smem_u32(const void* p) {
    uint32_t a;
    asm("{ .reg .u64 t; cvta.to.shared.u64 t, %1; cvt.u32.u64 %0, t; }" : "=r"(a) : "l"(p));
    return a;
}
__device__ __forceinline__ uint32_t sw128(uint32_t o) { return o ^ ((o >> 3) & 0x70); }

#define CP16(dst, src) \
    asm volatile("cp.async.cg.shared.global [%0], [%1], 16;" :: "r"(dst), "l"(src))
#define CP_COMMIT() asm volatile("cp.async.commit_group;" ::: "memory")
#define CP_WAIT1()  asm volatile("cp.async.wait_group 1;" ::: "memory")
#define CP_WAIT0()  asm volatile("cp.async.wait_group 0;" ::: "memory")

__device__ __forceinline__ void ldsm4(uint32_t (&r)[4], uint32_t addr) {
    asm volatile("ldmatrix.sync.aligned.m8n8.x4.shared.b16 {%0,%1,%2,%3}, [%4];"
                 : "=r"(r[0]), "=r"(r[1]), "=r"(r[2]), "=r"(r[3]) : "r"(addr));
}
__device__ __forceinline__ void mma16816(float (&c)[4], const uint32_t (&a)[4],
                                         uint32_t b0, uint32_t b1) {
    asm volatile(
        "mma.sync.aligned.m16n8k16.row.col.f32.f16.f16.f32 "
        "{%0,%1,%2,%3}, {%4,%5,%6,%7}, {%8,%9}, {%0,%1,%2,%3};"
        : "+f"(c[0]), "+f"(c[1]), "+f"(c[2]), "+f"(c[3])
        : "r"(a[0]), "r"(a[1]), "r"(a[2]), "r"(a[3]), "r"(b0), "r"(b1));
}

// ---------------------------------------------------------------------------
// pack: x[n][16] f32 (n = p*256+i) -> g_xh[d][n] fp16. CTA tile: 512 n-rows.
// ---------------------------------------------------------------------------
__global__ void __launch_bounds__(256) pack_kernel(const float* __restrict__ x) {
    __shared__ __half sh[16][528];
    const int n0 = blockIdx.x * 512;
    const int tid = threadIdx.x;
#pragma unroll
    for (int t = 0; t < 8; t++) {
        int id = tid + t * 256;
        int n = id >> 2, dq = id & 3;
        float4 v = reinterpret_cast<const float4*>(x)[(size_t)(n0 + n) * 4 + dq];
        sh[dq * 4 + 0][n] = __float2half_rn(v.x);
        sh[dq * 4 + 1][n] = __float2half_rn(v.y);
        sh[dq * 4 + 2][n] = __float2half_rn(v.z);
        sh[dq * 4 + 3][n] = __float2half_rn(v.w);
    }
    __syncthreads();
#pragma unroll
    for (int j = 0; j < 4; j++) {
        int u = j * 256 + tid;
        int d = u >> 6, c = u & 63;
        uint4 v = *reinterpret_cast<const uint4*>(&sh[d][c * 8]);
        *reinterpret_cast<uint4*>(&g_xh[d][n0 + c * 8]) = v;
    }
}

// ---------------------------------------------------------------------------
__global__ void __launch_bounds__(256) wsplit_kernel(const float* __restrict__ W00,
                                                     const float* __restrict__ W10,
                                                     const float* __restrict__ W11) {
    int i = blockIdx.x * 256 + threadIdx.x;
    if (i >= 3 * 65536) return;
    int w = i >> 16, j = i & 65535;
    const float* src = (w == 0) ? W00 : ((w == 1) ? W10 : W11);
    g_Wh[w][j] = __float2half_rn(src[j]);
}

// ---------------------------------------------------------------------------
// GEMM: grid 2048 = 256 pt x 2 dg x 4 ot ; bid = pt*8 + dg*4 + ot
// CTA: 32p x 64o x 8d, K=256 in 4 chunks of 64, cp.async double-buffered.
// stage: A[8d][32p][64k] (32KB) + B[3slot][64o][64k] (24KB) = 56KB; x2 = 112KB.
// ---------------------------------------------------------------------------
static constexpr int A_TILE = 32 * 128;           // 4 KB per d
static constexpr int B_TILE = 64 * 128;           // 8 KB per slot
static constexpr int SM_B   = 8 * A_TILE;         // 32768
static constexpr int STAGE  = SM_B + 3 * B_TILE;  // 57344
static constexpr int SMEMSZ = 2 * STAGE;          // 114688 -> 2 CTAs/SM

// slot map as constexpr functions (no static-array ODR issue in device code)
template <int DG>
__host__ __device__ constexpr int slot_of(int d) {
    return (DG == 0) ? ((d == 0) ? 0 : ((d < 7) ? 1 : 2)) : 0;
}
template <int DG>
__host__ __device__ constexpr int nslots() { return (DG == 0) ? 3 : 1; }

template <int DG>
__device__ __forceinline__ void gemm_body(const float* __restrict__ x,
                                          float* __restrict__ out, char* smem) {
    constexpr int NS = nslots<DG>();
    const uint32_t sb = smem_u32(smem);
    const int tid = threadIdx.x;
    const int lane = tid & 31, wid = tid >> 5;
    const int wp = wid >> 2, wo = wid & 3;       // 2 p-warps x 4 o-warps
    const int g = lane >> 2, c2 = lane & 3;

    const int bid = blockIdx.x;
    const int p0 = (bid >> 3) * 32, o0 = (bid & 3) * 64;

    // cp.async assignment: A: all 256 thr (d = tid>>5, row = tid&31), 8 x CP16
    //                      B: thr < NS*64 (slot = tid>>6, row = tid&63), 8 x CP16
    const int arow = tid & 31, asub = tid >> 5;
    const __half* aSrc = &g_xh[DG * 8 + asub][(size_t)(p0 + arow) * 256];
    const int bslot = tid >> 6;
    const int wsel = (DG == 0) ? (bslot < 3 ? bslot : 2) : 2;
    const __half* bSrc = g_Wh[wsel] + (size_t)(o0 + (tid & 63)) * 256;
    const bool doB = bslot < NS;

    float acc[8][2][4];
#pragma unroll
    for (int d = 0; d < 8; d++)
#pragma unroll
        for (int n2 = 0; n2 < 2; n2++)
#pragma unroll
            for (int e = 0; e < 4; e++) acc[d][n2][e] = 0.f;

    auto issue = [&](int c, int b) {
        uint32_t s0 = sb + b * STAGE;
        const __half* as = aSrc + c * 64;
#pragma unroll
        for (int q = 0; q < 8; q++)
            CP16(s0 + asub * A_TILE + sw128((uint32_t)(arow * 128 + q * 16)), as + q * 8);
        if (doB) {
            const __half* bs = bSrc + c * 64;
            uint32_t bt = s0 + SM_B + bslot * B_TILE;
#pragma unroll
            for (int q = 0; q < 8; q++)
                CP16(bt + sw128((uint32_t)((tid & 63) * 128 + q * 16)), bs + q * 8);
        }
        CP_COMMIT();
    };

    auto compute = [&](int b) {
        uint32_t s0 = sb + b * STAGE;
        const uint32_t rowB = (uint32_t)(wo * 16 + (lane & 15)) * 128;
        const uint32_t rowA = (uint32_t)(wp * 16 + (lane & 15)) * 128;
#pragma unroll
        for (int s = 0; s < 4; s++) {
            const uint32_t qb = (uint32_t)(s * 2 + (lane >> 4)) * 16;
            uint32_t bf[NS][4];
#pragma unroll
            for (int u = 0; u < NS; u++)
                ldsm4(bf[u], s0 + SM_B + u * B_TILE + sw128(rowB + qb));
#pragma unroll
            for (int d = 0; d < 8; d++) {
                uint32_t a[4];
                ldsm4(a, s0 + d * A_TILE + sw128(rowA + qb));
                const uint32_t* B = bf[slot_of<DG>(d)];
                mma16816(acc[d][0], a, B[0], B[2]);
                mma16816(acc[d][1], a, B[1], B[3]);
            }
        }
    };

    issue(0, 0);
#pragma unroll
    for (int c = 0; c < 4; c++) {
        if (c + 1 < 4) { issue(c + 1, (c + 1) & 1); CP_WAIT1(); }
        else           { CP_WAIT0(); }
        __syncthreads();
        compute(c & 1);
        __syncthreads();
    }

    // epilogue: acc + residual -> 2x float4 (32B = one DRAM sector) per point
#pragma unroll
    for (int n2 = 0; n2 < 2; n2++)
#pragma unroll
        for (int e = 0; e < 4; e++) {
            int p = p0 + wp * 16 + g + (e >> 1) * 8;
            int o = o0 + wo * 16 + n2 * 8 + c2 * 2 + (e & 1);
            size_t go = (size_t)p * 4096 + (size_t)o * 16 + DG * 8;
            float4 r0 = *reinterpret_cast<const float4*>(x + go);
            float4 r1 = *reinterpret_cast<const float4*>(x + go + 4);
            float4 v0, v1;
            v0.x = acc[0][n2][e] + r0.x;
            v0.y = acc[1][n2][e] + r0.y;
            v0.z = acc[2][n2][e] + r0.z;
            v0.w = acc[3][n2][e] + r0.w;
            v1.x = acc[4][n2][e] + r1.x;
            v1.y = acc[5][n2][e] + r1.y;
            v1.z = acc[6][n2][e] + r1.z;
            v1.w = acc[7][n2][e] + r1.w;
            *reinterpret_cast<float4*>(out + go) = v0;
            *reinterpret_cast<float4*>(out + go + 4) = v1;
        }
}

__global__ void __launch_bounds__(256, 2)
gemm_kernel(const float* __restrict__ x, float* __restrict__ out) {
    extern __shared__ char smem[];
    if (((blockIdx.x >> 2) & 1) == 0) gemm_body<0>(x, out, smem);
    else                              gemm_body<1>(x, out, smem);
}

// ---------------------------------------------------------------------------
extern "C" void kernel_launch(void* const* d_in, const int* in_sizes, int n_in,
                              void* d_out, int out_size) {
    const float* x   = (const float*)d_in[0];
    const float* W00 = (const float*)d_in[1];
    const float* W10 = (const float*)d_in[2];
    const float* W11 = (const float*)d_in[3];
    float* out = (float*)d_out;

    pack_kernel<<<PC / 512, 256>>>(x);
    wsplit_kernel<<<768, 256>>>(W00, W10, W11);

    cudaFuncSetAttribute(gemm_kernel,
                         cudaFuncAttributeMaxDynamicSharedMemorySize, SMEMSZ);
    gemm_kernel<<<2048, 256, SMEMSZ>>>(x, out);
}

// round 9
// speedup vs baseline: 1.2650x; 1.2650x over previous
#include <cuda_runtime.h>
#include <cuda_fp16.h>
#include <cstdint>

// ============================================================================
// GLinear, plain sm_103 target (no tcgen05 in this toolchain):
//   pack:   x[P,C,16] f32 -> 16 fp16 planes g_xh[d][P*C]  (coalesced transpose)
//   wsplit: W f32 -> fp16
//   gemm:   PERSISTENT: 128 CTAs (1/SM, 512 thr). CTA owns (dg,ot), loops over
//           8 p-tiles of 128p x 64o x 4d. B (2 slots, full K=256) loaded into
//           smem ONCE; A double-buffered k64 chunks via cp.async; ldmatrix +
//           mma.sync m16n8k16 fp16->fp32; fused residual + float4 stores.
// ============================================================================

static constexpr int PC = 8192 * 256;            // 2097152
__device__ __half g_xh[16][PC];                  // 64 MB packed x (fp16)
__device__ __half g_Wh[3][65536];

// ---------------------------------------------------------------------------
__device__ __forceinline__ uint32_t smem_u32(const void* p) {
    uint32_t a;
    asm("{ .reg .u64 t; cvta.to.shared.u64 t, %1; cvt.u32.u64 %0, t; }" : "=r"(a) : "l"(p));
    return a;
}
__device__ __forceinline__ uint32_t sw128(uint32_t o) { return o ^ ((o >> 3) & 0x70); }

#define CP16(dst, src) \
    asm volatile("cp.async.cg.shared.global [%0], [%1], 16;" :: "r"(dst), "l"(src))
#define CP_COMMIT() asm volatile("cp.async.commit_group;" ::: "memory")
#define CP_WAIT1()  asm volatile("cp.async.wait_group 1;" ::: "memory")
#define CP_WAIT0()  asm volatile("cp.async.wait_group 0;" ::: "memory")

__device__ __forceinline__ void ldsm4(uint32_t (&r)[4], uint32_t addr) {
    asm volatile("ldmatrix.sync.aligned.m8n8.x4.shared.b16 {%0,%1,%2,%3}, [%4];"
                 : "=r"(r[0]), "=r"(r[1]), "=r"(r[2]), "=r"(r[3]) : "r"(addr));
}
__device__ __forceinline__ void mma16816(float (&c)[4], const uint32_t (&a)[4],
                                         uint32_t b0, uint32_t b1) {
    asm volatile(
        "mma.sync.aligned.m16n8k16.row.col.f32.f16.f16.f32 "
        "{%0,%1,%2,%3}, {%4,%5,%6,%7}, {%8,%9}, {%0,%1,%2,%3};"
        : "+f"(c[0]), "+f"(c[1]), "+f"(c[2]), "+f"(c[3])
        : "r"(a[0]), "r"(a[1]), "r"(a[2]), "r"(a[3]), "r"(b0), "r"(b1));
}

// ---------------------------------------------------------------------------
// pack: x[n][16] f32 (n = p*256+i) -> g_xh[d][n] fp16. CTA tile: 512 n-rows.
// ---------------------------------------------------------------------------
__global__ void __launch_bounds__(256) pack_kernel(const float* __restrict__ x) {
    __shared__ __half sh[16][528];
    const int n0 = blockIdx.x * 512;
    const int tid = threadIdx.x;
#pragma unroll
    for (int t = 0; t < 8; t++) {
        int id = tid + t * 256;
        int n = id >> 2, dq = id & 3;
        float4 v = reinterpret_cast<const float4*>(x)[(size_t)(n0 + n) * 4 + dq];
        sh[dq * 4 + 0][n] = __float2half_rn(v.x);
        sh[dq * 4 + 1][n] = __float2half_rn(v.y);
        sh[dq * 4 + 2][n] = __float2half_rn(v.z);
        sh[dq * 4 + 3][n] = __float2half_rn(v.w);
    }
    __syncthreads();
#pragma unroll
    for (int j = 0; j < 4; j++) {
        int u = j * 256 + tid;
        int d = u >> 6, c = u & 63;
        uint4 v = *reinterpret_cast<const uint4*>(&sh[d][c * 8]);
        *reinterpret_cast<uint4*>(&g_xh[d][n0 + c * 8]) = v;
    }
}

// ---------------------------------------------------------------------------
__global__ void __launch_bounds__(256) wsplit_kernel(const float* __restrict__ W00,
                                                     const float* __restrict__ W10,
                                                     const float* __restrict__ W11) {
    int i = blockIdx.x * 256 + threadIdx.x;
    if (i >= 3 * 65536) return;
    int w = i >> 16, j = i & 65535;
    const float* src = (w == 0) ? W00 : ((w == 1) ? W10 : W11);
    g_Wh[w][j] = __float2half_rn(src[j]);
}

// ---------------------------------------------------------------------------
// Persistent GEMM.
// grid 128: bid -> dg = bid>>5, ot = (bid>>3)&3, j = bid&7.
// CTA loops t = 0..7 over p-tiles p0 = (t*8 + j)*128  (ot-siblings share A via L2).
// smem: A: 2 buffers x [4d][128p][128B sw128] = 2 x 64KB
//       B: [4 kc][2 slot][64o][128B sw128]    = 64KB   (loaded once)
// ---------------------------------------------------------------------------
static constexpr int A_D   = 128 * 128;          // 16 KB per d per buffer
static constexpr int A_BUF = 4 * A_D;            // 64 KB
static constexpr int SM_B  = 2 * A_BUF;          // 131072
static constexpr int B_T   = 64 * 128;           // 8 KB per (kc,slot)
static constexpr int SMEMSZ = SM_B + 8 * B_T;    // 196608 (192 KB)

static constexpr int NTILE = 8;
static constexpr int NIT   = NTILE * 4;          // 32 chunk-iterations

__global__ void __launch_bounds__(512, 1)
gemm_kernel(const float* __restrict__ x, float* __restrict__ out) {
    extern __shared__ char smem[];
    const uint32_t sb = smem_u32(smem);
    const int tid = threadIdx.x;
    const int lane = tid & 31, wid = tid >> 5;
    const int wp = wid >> 2, wo = wid & 3;        // 4 p-warps x 4 o-warps
    const int g = lane >> 2, c2 = lane & 3;

    const int bid = blockIdx.x;
    const int dg = bid >> 5, ot = (bid >> 3) & 3, j = bid & 7;
    const int o0 = ot * 64;

    // W mapping for this d-group (<=2 distinct W -> 2 slots)
    int w_of[4];
#pragma unroll
    for (int dd = 0; dd < 4; dd++) {
        int d = dg * 4 + dd;
        w_of[dd] = (d == 0) ? 0 : ((d < 7) ? 1 : 2);
    }
    int w0 = w_of[0], w1 = w0;
#pragma unroll
    for (int dd = 1; dd < 4; dd++)
        if (w_of[dd] != w0) w1 = w_of[dd];
    int slot_of[4];
#pragma unroll
    for (int dd = 0; dd < 4; dd++) slot_of[dd] = (w_of[dd] == w0) ? 0 : 1;

    // ---- B load (once): tid -> kc = tid>>7, slot = (tid>>6)&1, orow = tid&63
    {
        const int kc = tid >> 7, slot = (tid >> 6) & 1, orow = tid & 63;
        const __half* bs = g_Wh[slot ? w1 : w0] + (size_t)(o0 + orow) * 256 + kc * 64;
        uint32_t bt = sb + SM_B + (kc * 2 + slot) * B_T;
#pragma unroll
        for (int q = 0; q < 8; q++)
            CP16(bt + sw128((uint32_t)(orow * 128 + q * 16)), bs + q * 8);
        CP_COMMIT();
    }

    // ---- A issue: flat n = tile*4 + chunk, buffer n&1
    const int ad = tid >> 7, arow = tid & 127;    // d, p-row for this thread
    const __half* aPlane = g_xh[dg * 4 + ad];
    auto issueA = [&](int n) {
        int t = n >> 2, c = n & 3;
        int p0 = (t * 8 + j) * 128;
        const __half* as = aPlane + (size_t)(p0 + arow) * 256 + c * 64;
        uint32_t s0 = sb + (n & 1) * A_BUF + ad * A_D;
#pragma unroll
        for (int q = 0; q < 8; q++)
            CP16(s0 + sw128((uint32_t)(arow * 128 + q * 16)), as + q * 8);
        CP_COMMIT();
    };

    float acc[4][2][2][4];
#pragma unroll
    for (int d = 0; d < 4; d++)
#pragma unroll
        for (int m = 0; m < 2; m++)
#pragma unroll
            for (int n2 = 0; n2 < 2; n2++)
#pragma unroll
                for (int e = 0; e < 4; e++) acc[d][m][n2][e] = 0.f;

    auto compute = [&](int b, int c) {
        uint32_t a0b = sb + b * A_BUF;
        uint32_t bbase = sb + SM_B + c * 2 * B_T;
        const uint32_t rowB = (uint32_t)(wo * 16 + (lane & 15)) * 128;
        const uint32_t rowA = (uint32_t)(wp * 32 + (lane & 15)) * 128;
#pragma unroll
        for (int s = 0; s < 4; s++) {
            const uint32_t qb = (uint32_t)(s * 2 + (lane >> 4)) * 16;
            uint32_t bf[2][4];
            ldsm4(bf[0], bbase + sw128(rowB + qb));
            ldsm4(bf[1], bbase + B_T + sw128(rowB + qb));
#pragma unroll
            for (int d = 0; d < 4; d++) {
                uint32_t a0[4], a1[4];
                ldsm4(a0, a0b + d * A_D + sw128(rowA + qb));
                ldsm4(a1, a0b + d * A_D + sw128(rowA + 16 * 128 + qb));
                const uint32_t* B = bf[slot_of[d]];
                mma16816(acc[d][0][0], a0, B[0], B[2]);
                mma16816(acc[d][0][1], a0, B[1], B[3]);
                mma16816(acc[d][1][0], a1, B[0], B[2]);
                mma16816(acc[d][1][1], a1, B[1], B[3]);
            }
        }
    };

    issueA(0);
    issueA(1);

    for (int n = 0; n < NIT; n++) {
        if (n == NIT - 1) { CP_WAIT0(); } else { CP_WAIT1(); }
        __syncthreads();
        compute(n & 1, n & 3);
        __syncthreads();
        if (n + 2 < NIT) issueA(n + 2);   // DMA overlaps epilogue below

        if ((n & 3) == 3) {
            // ---- per-tile epilogue: acc + residual -> float4 stores ----
            int t = n >> 2;
            int p0 = (t * 8 + j) * 128;
#pragma unroll
            for (int m = 0; m < 2; m++)
#pragma unroll
                for (int n2 = 0; n2 < 2; n2++)
#pragma unroll
                    for (int e = 0; e < 4; e++) {
                        int p = p0 + wp * 32 + m * 16 + g + (e >> 1) * 8;
                        int o = o0 + wo * 16 + n2 * 8 + c2 * 2 + (e & 1);
                        size_t go = (size_t)p * 4096 + (size_t)o * 16 + dg * 4;
                        float4 r = *reinterpret_cast<const float4*>(x + go);
                        float4 v;
                        v.x = acc[0][m][n2][e] + r.x;
                        v.y = acc[1][m][n2][e] + r.y;
                        v.z = acc[2][m][n2][e] + r.z;
                        v.w = acc[3][m][n2][e] + r.w;
                        *reinterpret_cast<float4*>(out + go) = v;
                        acc[0][m][n2][e] = 0.f; acc[1][m][n2][e] = 0.f;
                        acc[2][m][n2][e] = 0.f; acc[3][m][n2][e] = 0.f;
                    }
        }
    }
}

// ---------------------------------------------------------------------------
extern "C" void kernel_launch(void* const* d_in, const int* in_sizes, int n_in,
                              void* d_out, int out_size) {
    const float* x   = (const float*)d_in[0];
    const float* W00 = (const float*)d_in[1];
    const float* W10 = (const float*)d_in[2];
    const float* W11 = (const float*)d_in[3];
    float* out = (float*)d_out;

    pack_kernel<<<PC / 512, 256>>>(x);
    wsplit_kernel<<<768, 256>>>(W00, W10, W11);

    cudaFuncSetAttribute(gemm_kernel,
                         cudaFuncAttributeMaxDynamicSharedMemorySize, SMEMSZ);
    gemm_kernel<<<128, 512, SMEMSZ>>>(x, out);
}